// round 2
// baseline (speedup 1.0000x reference)
#include <cuda_runtime.h>
#include <cuda_bf16.h>

// Problem constants (fixed by the reference): N=100000 nodes, E=1280000 edges, D=64.
#define MAX_N 100000
#define MAX_E 1280000

// Scratch (no cudaMalloc allowed) — device globals.
__device__ float g_asrc[MAX_N];
__device__ float g_adst[MAX_N];
__device__ float g_coef[MAX_E];

// ---------------------------------------------------------------------------
// Kernel 1: per-node scalar scores  a_src[n] = x[n,:]·w_src, a_dst[n] = x[n,:]·w_dst
// One warp per node; each lane covers 2 of the 64 features.
// ---------------------------------------------------------------------------
__global__ void node_scores_kernel(const float* __restrict__ x,
                                   const float* __restrict__ w_src,
                                   const float* __restrict__ w_dst,
                                   int n_nodes) {
    int gtid = blockIdx.x * blockDim.x + threadIdx.x;
    int node = gtid >> 5;
    int lane = gtid & 31;
    if (node >= n_nodes) return;

    const float* xr = x + (size_t)node * 64;
    float v0 = xr[lane];
    float v1 = xr[lane + 32];
    float ws0 = __ldg(w_src + lane);
    float ws1 = __ldg(w_src + lane + 32);
    float wd0 = __ldg(w_dst + lane);
    float wd1 = __ldg(w_dst + lane + 32);

    float ss = v0 * ws0 + v1 * ws1;
    float sd = v0 * wd0 + v1 * wd1;

    #pragma unroll
    for (int off = 16; off > 0; off >>= 1) {
        ss += __shfl_down_sync(0xffffffffu, ss, off);
        sd += __shfl_down_sync(0xffffffffu, sd, off);
    }
    if (lane == 0) {
        g_asrc[node] = ss;
        g_adst[node] = sd;
    }
}

// ---------------------------------------------------------------------------
// Kernel 2: per-edge coefficient  coef[e] = tanh(a_src[src] + a_dst[dst]) * ew[e]
// ---------------------------------------------------------------------------
__global__ void edge_coef_kernel(const int* __restrict__ src_idx,
                                 const int* __restrict__ dst_idx,
                                 const float* __restrict__ ew,
                                 int n_edges) {
    int e = blockIdx.x * blockDim.x + threadIdx.x;
    if (e >= n_edges) return;
    int s = __ldg(src_idx + e);
    int d = __ldg(dst_idx + e);
    float a = g_asrc[s] + g_adst[d];
    g_coef[e] = tanhf(a) * __ldg(ew + e);
}

// ---------------------------------------------------------------------------
// Kernel 3: scatter  h[dst,:] += coef[e] * x[src,:]
// 16 threads per edge; each thread handles one float4 (4 of the 64 features).
// Uses vector reduction red.global.add.v4.f32 (sm_90+) to quarter atomic count.
// ---------------------------------------------------------------------------
__global__ void scatter_kernel(const float* __restrict__ x,
                               const int* __restrict__ src_idx,
                               const int* __restrict__ dst_idx,
                               float* __restrict__ out,
                               int n_edges) {
    int t = blockIdx.x * blockDim.x + threadIdx.x;
    int e = t >> 4;
    if (e >= n_edges) return;
    int q = t & 15;

    int s = __ldg(src_idx + e);   // 16 lanes same addr -> L1 broadcast
    int d = __ldg(dst_idx + e);
    float c = g_coef[e];

    const float4* xr = reinterpret_cast<const float4*>(x) + (size_t)s * 16 + q;
    float4 xv = __ldg(xr);
    float4 m;
    m.x = c * xv.x;
    m.y = c * xv.y;
    m.z = c * xv.z;
    m.w = c * xv.w;

    float* p = out + (size_t)d * 64 + q * 4;
    asm volatile("red.global.add.v4.f32 [%0], {%1, %2, %3, %4};"
                 :: "l"(p), "f"(m.x), "f"(m.y), "f"(m.z), "f"(m.w)
                 : "memory");
}

// ---------------------------------------------------------------------------
// Launch
// Inputs (metadata order): x[N*64] f32, w_src[64] f32, w_dst[64] f32,
//                          ew[E] f32, src_idx[E] i32, dst_idx[E] i32
// Output: h[N*64] f32
// ---------------------------------------------------------------------------
extern "C" void kernel_launch(void* const* d_in, const int* in_sizes, int n_in,
                              void* d_out, int out_size) {
    const float* x     = (const float*)d_in[0];
    const float* w_src = (const float*)d_in[1];
    const float* w_dst = (const float*)d_in[2];
    const float* ew    = (const float*)d_in[3];
    const int*   s_idx = (const int*)d_in[4];
    const int*   d_idx = (const int*)d_in[5];
    float* out = (float*)d_out;

    int n_nodes = in_sizes[0] / 64;
    int n_edges = in_sizes[3];

    // Zero the output (poisoned by harness). Memset node is graph-capturable.
    cudaMemsetAsync(out, 0, (size_t)out_size * sizeof(float));

    {
        int threads = 256;
        int total = n_nodes * 32;               // warp per node
        int blocks = (total + threads - 1) / threads;
        node_scores_kernel<<<blocks, threads>>>(x, w_src, w_dst, n_nodes);
    }
    {
        int threads = 256;
        int blocks = (n_edges + threads - 1) / threads;
        edge_coef_kernel<<<blocks, threads>>>(s_idx, d_idx, ew, n_edges);
    }
    {
        int threads = 256;
        long long total = (long long)n_edges * 16;  // 16 threads per edge
        int blocks = (int)((total + threads - 1) / threads);
        scatter_kernel<<<blocks, threads>>>(x, s_idx, d_idx, out, n_edges);
    }
}

// round 3
// speedup vs baseline: 1.1320x; 1.1320x over previous
#include <cuda_runtime.h>
#include <cuda_bf16.h>

// Fixed problem sizes: N=100000 nodes, E=1280000 edges, D=64.
#define N_NODES 100000
#define N_EDGES 1280000
#define SCAN_BLK 256
#define NB_SCAN ((N_NODES + SCAN_BLK - 1) / SCAN_BLK)   // 391

// Device-global scratch (no cudaMalloc allowed).
__device__ float g_asrc[N_NODES];
__device__ float g_adst[N_NODES];
__device__ int   g_cnt[N_NODES];
__device__ int   g_off[N_NODES + 1];
__device__ int   g_pos[N_NODES];
__device__ int   g_part[NB_SCAN];
__device__ uint2 g_pair[N_EDGES];      // (src, coef-bits) sorted by dst bin

// ---------------------------------------------------------------------------
// Per-node scalar scores. 16 threads/node, one float4 each, 4-step shfl reduce.
// ---------------------------------------------------------------------------
__global__ void node_scores_kernel(const float4* __restrict__ x4,
                                   const float4* __restrict__ ws4,
                                   const float4* __restrict__ wd4,
                                   int n_nodes) {
    int t = blockIdx.x * blockDim.x + threadIdx.x;
    int node = t >> 4;
    int q = t & 15;
    if (node >= n_nodes) return;

    float4 v  = __ldg(x4 + (size_t)node * 16 + q);
    float4 ws = __ldg(ws4 + q);
    float4 wd = __ldg(wd4 + q);

    float ss = v.x * ws.x + v.y * ws.y + v.z * ws.z + v.w * ws.w;
    float sd = v.x * wd.x + v.y * wd.y + v.z * wd.z + v.w * wd.w;

    #pragma unroll
    for (int off = 8; off > 0; off >>= 1) {
        ss += __shfl_down_sync(0xffffffffu, ss, off, 16);
        sd += __shfl_down_sync(0xffffffffu, sd, off, 16);
    }
    if (q == 0) {
        g_asrc[node] = ss;
        g_adst[node] = sd;
    }
}

// ---------------------------------------------------------------------------
// Histogram of dst indices.
// ---------------------------------------------------------------------------
__global__ void hist_kernel(const int* __restrict__ dst_idx, int n_edges) {
    int e = blockIdx.x * blockDim.x + threadIdx.x;
    if (e < n_edges) atomicAdd(&g_cnt[__ldg(dst_idx + e)], 1);
}

// ---------------------------------------------------------------------------
// Scan phase A: per-block (256) exclusive scan of g_cnt -> g_off (local),
// block totals -> g_part.
// ---------------------------------------------------------------------------
__global__ void scanA_kernel(int n) {
    int i = blockIdx.x * SCAN_BLK + threadIdx.x;
    int v = (i < n) ? g_cnt[i] : 0;
    int lane = threadIdx.x & 31;
    int w = threadIdx.x >> 5;

    int incl = v;
    #pragma unroll
    for (int d = 1; d < 32; d <<= 1) {
        int u = __shfl_up_sync(0xffffffffu, incl, d);
        if (lane >= d) incl += u;
    }

    __shared__ int wsum[8];
    if (lane == 31) wsum[w] = incl;
    __syncthreads();
    if (w == 0 && lane < 8) {
        int s = wsum[lane];
        int si = s;
        #pragma unroll
        for (int d = 1; d < 8; d <<= 1) {
            int u = __shfl_up_sync(0x000000ffu, si, d);
            if (lane >= d) si += u;
        }
        wsum[lane] = si - s;   // exclusive warp-sum prefix
    }
    __syncthreads();

    int excl = incl - v + wsum[w];
    if (i < n) g_off[i] = excl;
    if (threadIdx.x == SCAN_BLK - 1) g_part[blockIdx.x] = incl + wsum[w];
}

// ---------------------------------------------------------------------------
// Scan phase B: single block scans the 391 block totals (exclusive, in place).
// ---------------------------------------------------------------------------
__global__ void scanB_kernel(int nb) {
    __shared__ int s[512];
    int t = threadIdx.x;
    int v = (t < nb) ? g_part[t] : 0;
    s[t] = v;
    __syncthreads();
    for (int d = 1; d < 512; d <<= 1) {
        int u = (t >= d) ? s[t - d] : 0;
        __syncthreads();
        s[t] += u;
        __syncthreads();
    }
    if (t < nb) g_part[t] = s[t] - v;   // exclusive
}

// ---------------------------------------------------------------------------
// Scan phase C: add block offsets; produce g_off (final) and g_pos (cursors).
// ---------------------------------------------------------------------------
__global__ void scanC_kernel(int n, int n_edges) {
    int i = blockIdx.x * blockDim.x + threadIdx.x;
    if (i < n) {
        int o = g_off[i] + g_part[i >> 8];
        g_off[i] = o;
        g_pos[i] = o;
    }
    if (i == 0) g_off[n] = n_edges;
}

// ---------------------------------------------------------------------------
// Permute + fused edge coefficient: coef = tanh(a_src[s]+a_dst[d])*ew,
// write packed (src, coef) into the dst bin.
// ---------------------------------------------------------------------------
__global__ void permute_kernel(const int* __restrict__ src_idx,
                               const int* __restrict__ dst_idx,
                               const float* __restrict__ ew,
                               int n_edges) {
    int e = blockIdx.x * blockDim.x + threadIdx.x;
    if (e >= n_edges) return;
    int s = __ldg(src_idx + e);
    int d = __ldg(dst_idx + e);
    float c = tanhf(g_asrc[s] + g_adst[d]) * __ldg(ew + e);
    int p = atomicAdd(&g_pos[d], 1);
    g_pair[p] = make_uint2((unsigned)s, __float_as_uint(c));
}

// ---------------------------------------------------------------------------
// Aggregate: 16 threads per dst node, register accumulation, single store.
// No atomics. Zero-degree nodes store zeros (covers the poisoned output).
// ---------------------------------------------------------------------------
__global__ void aggregate_kernel(const float4* __restrict__ x4,
                                 float4* __restrict__ out4,
                                 int n_nodes) {
    int t = blockIdx.x * blockDim.x + threadIdx.x;
    int node = t >> 4;
    int q = t & 15;
    if (node >= n_nodes) return;

    int beg = g_off[node];
    int end = g_off[node + 1];

    float4 acc = make_float4(0.f, 0.f, 0.f, 0.f);

    int i = beg;
    if (i < end) {
        uint2 pr = __ldg(&g_pair[i]);
        for (++i; i < end; ++i) {
            uint2 nx = __ldg(&g_pair[i]);          // prefetch next pair
            float  c  = __uint_as_float(pr.y);
            float4 xv = __ldg(x4 + (size_t)pr.x * 16 + q);
            acc.x += c * xv.x;
            acc.y += c * xv.y;
            acc.z += c * xv.z;
            acc.w += c * xv.w;
            pr = nx;
        }
        float  c  = __uint_as_float(pr.y);
        float4 xv = __ldg(x4 + (size_t)pr.x * 16 + q);
        acc.x += c * xv.x;
        acc.y += c * xv.y;
        acc.z += c * xv.z;
        acc.w += c * xv.w;
    }

    out4[(size_t)node * 16 + q] = acc;
}

// ---------------------------------------------------------------------------
// Launch.
// Inputs: x[N*64] f32, w_src[64] f32, w_dst[64] f32, ew[E] f32,
//         src_idx[E] i32, dst_idx[E] i32.  Output: h[N*64] f32.
// ---------------------------------------------------------------------------
extern "C" void kernel_launch(void* const* d_in, const int* in_sizes, int n_in,
                              void* d_out, int out_size) {
    const float* x     = (const float*)d_in[0];
    const float* w_src = (const float*)d_in[1];
    const float* w_dst = (const float*)d_in[2];
    const float* ew    = (const float*)d_in[3];
    const int*   s_idx = (const int*)d_in[4];
    const int*   d_idx = (const int*)d_in[5];
    float* out = (float*)d_out;

    int n_nodes = in_sizes[0] / 64;
    int n_edges = in_sizes[3];

    // Zero the dst histogram (memset node is graph-capturable).
    void* cnt_ptr = nullptr;
    cudaGetSymbolAddress(&cnt_ptr, g_cnt);
    cudaMemsetAsync(cnt_ptr, 0, sizeof(int) * (size_t)n_nodes);

    {   // node scores: 16 threads/node
        long long total = (long long)n_nodes * 16;
        int blocks = (int)((total + 255) / 256);
        node_scores_kernel<<<blocks, 256>>>((const float4*)x, (const float4*)w_src,
                                            (const float4*)w_dst, n_nodes);
    }
    {   // histogram
        int blocks = (n_edges + 255) / 256;
        hist_kernel<<<blocks, 256>>>(d_idx, n_edges);
    }
    {   // 3-phase prefix scan over n_nodes counters
        int nb = (n_nodes + SCAN_BLK - 1) / SCAN_BLK;
        scanA_kernel<<<nb, SCAN_BLK>>>(n_nodes);
        scanB_kernel<<<1, 512>>>(nb);
        scanC_kernel<<<(n_nodes + 255) / 256, 256>>>(n_nodes, n_edges);
    }
    {   // permute with fused coefficient computation
        int blocks = (n_edges + 255) / 256;
        permute_kernel<<<blocks, 256>>>(s_idx, d_idx, ew, n_edges);
    }
    {   // aggregate: 16 threads/node
        long long total = (long long)n_nodes * 16;
        int blocks = (int)((total + 255) / 256);
        aggregate_kernel<<<blocks, 256>>>((const float4*)x, (float4*)out, n_nodes);
    }
}

// round 4
// speedup vs baseline: 1.2248x; 1.0820x over previous
#include <cuda_runtime.h>
#include <cuda_bf16.h>

// Fixed problem sizes: N=100000 nodes, E=1280000 edges, D=64.
#define N_NODES 100000
#define N_EDGES 1280000
#define SCAN_BLK 256
#define NB_SCAN ((N_NODES + SCAN_BLK - 1) / SCAN_BLK)   // 391

// Device-global scratch (no cudaMalloc allowed).
__device__ float g_asrc[N_NODES];
__device__ float g_adst[N_NODES];
__device__ int   g_cnt[N_NODES];       // hist counts, then local-scanned copy source
__device__ int   g_off[N_NODES];       // block-local exclusive prefix of cnt
__device__ int   g_part[NB_SCAN];      // per-block totals -> exclusive block prefix
__device__ int   g_rank[N_EDGES];      // rank of edge within its dst bin
__device__ uint2 g_pair[N_EDGES];      // (src, coef-bits) grouped by dst

// ---------------------------------------------------------------------------
// K1 (fused): per-node scores (16 threads/node, float4 each) + dst histogram
// with per-edge rank recording. The two jobs are independent grid-stride work.
// ---------------------------------------------------------------------------
__global__ void scores_hist_kernel(const float4* __restrict__ x4,
                                   const float4* __restrict__ ws4,
                                   const float4* __restrict__ wd4,
                                   const int* __restrict__ dst_idx,
                                   int n_nodes, int n_edges) {
    int t = blockIdx.x * blockDim.x + threadIdx.x;

    // --- job A: node scores ---
    int node = t >> 4;
    int q = t & 15;
    if (node < n_nodes) {
        float4 v  = __ldg(x4 + (size_t)node * 16 + q);
        float4 ws = __ldg(ws4 + q);
        float4 wd = __ldg(wd4 + q);

        float ss = v.x * ws.x + v.y * ws.y + v.z * ws.z + v.w * ws.w;
        float sd = v.x * wd.x + v.y * wd.y + v.z * wd.z + v.w * wd.w;

        #pragma unroll
        for (int off = 8; off > 0; off >>= 1) {
            ss += __shfl_down_sync(0xffffffffu, ss, off, 16);
            sd += __shfl_down_sync(0xffffffffu, sd, off, 16);
        }
        if (q == 0) {
            g_asrc[node] = ss;
            g_adst[node] = sd;
        }
    }

    // --- job B: histogram + rank ---
    if (t < n_edges) {
        int d = __ldg(dst_idx + t);
        g_rank[t] = atomicAdd(&g_cnt[d], 1);
    }
}

// ---------------------------------------------------------------------------
// Scan phase A: per-block (256) exclusive scan of g_cnt -> g_off (local),
// block totals -> g_part.
// ---------------------------------------------------------------------------
__global__ void scanA_kernel(int n) {
    int i = blockIdx.x * SCAN_BLK + threadIdx.x;
    int v = (i < n) ? g_cnt[i] : 0;
    int lane = threadIdx.x & 31;
    int w = threadIdx.x >> 5;

    int incl = v;
    #pragma unroll
    for (int d = 1; d < 32; d <<= 1) {
        int u = __shfl_up_sync(0xffffffffu, incl, d);
        if (lane >= d) incl += u;
    }

    __shared__ int wsum[8];
    if (lane == 31) wsum[w] = incl;
    __syncthreads();
    if (w == 0 && lane < 8) {
        int s = wsum[lane];
        int si = s;
        #pragma unroll
        for (int d = 1; d < 8; d <<= 1) {
            int u = __shfl_up_sync(0x000000ffu, si, d);
            if (lane >= d) si += u;
        }
        wsum[lane] = si - s;   // exclusive warp-sum prefix
    }
    __syncthreads();

    int excl = incl - v + wsum[w];
    if (i < n) g_off[i] = excl;
    if (threadIdx.x == SCAN_BLK - 1) g_part[blockIdx.x] = incl + wsum[w];
}

// ---------------------------------------------------------------------------
// Scan phase B: exclusive scan of the 391 block totals, 2-level shfl scan.
// ---------------------------------------------------------------------------
__global__ void scanB_kernel(int nb) {
    int t = threadIdx.x;
    int lane = t & 31;
    int w = t >> 5;
    int v = (t < nb) ? g_part[t] : 0;

    int incl = v;
    #pragma unroll
    for (int d = 1; d < 32; d <<= 1) {
        int u = __shfl_up_sync(0xffffffffu, incl, d);
        if (lane >= d) incl += u;
    }

    __shared__ int wsum[16];
    if (lane == 31) wsum[w] = incl;
    __syncthreads();
    if (w == 0 && lane < 16) {
        int s = wsum[lane];
        int si = s;
        #pragma unroll
        for (int d = 1; d < 16; d <<= 1) {
            int u = __shfl_up_sync(0x0000ffffu, si, d);
            if (lane >= d) si += u;
        }
        wsum[lane] = si - s;
    }
    __syncthreads();

    if (t < nb) g_part[t] = incl - v + wsum[w];
}

// ---------------------------------------------------------------------------
// Permute + fused edge coefficient: coef = tanh(a_src[s]+a_dst[d])*ew.
// Destination slot computed WITHOUT atomics: local off + block prefix + rank.
// ---------------------------------------------------------------------------
__global__ void permute_kernel(const int* __restrict__ src_idx,
                               const int* __restrict__ dst_idx,
                               const float* __restrict__ ew,
                               int n_edges) {
    int e = blockIdx.x * blockDim.x + threadIdx.x;
    if (e >= n_edges) return;
    int s = __ldg(src_idx + e);
    int d = __ldg(dst_idx + e);
    float c = tanhf(g_asrc[s] + g_adst[d]) * __ldg(ew + e);
    int p = g_off[d] + g_part[d >> 8] + g_rank[e];
    g_pair[p] = make_uint2((unsigned)s, __float_as_uint(c));
}

// ---------------------------------------------------------------------------
// Aggregate: 16 threads per dst node, register accumulation, 2-way unrolled
// for MLP=2 on the x gathers. No atomics; single store per output float4.
// ---------------------------------------------------------------------------
__global__ void aggregate_kernel(const float4* __restrict__ x4,
                                 float4* __restrict__ out4,
                                 int n_nodes, int n_edges) {
    int t = blockIdx.x * blockDim.x + threadIdx.x;
    int node = t >> 4;
    int q = t & 15;
    if (node >= n_nodes) return;

    int beg = g_off[node] + g_part[node >> 8];
    int end = (node + 1 < n_nodes)
                  ? g_off[node + 1] + g_part[(node + 1) >> 8]
                  : n_edges;

    float4 acc = make_float4(0.f, 0.f, 0.f, 0.f);

    int i = beg;
    for (; i + 1 < end; i += 2) {
        uint2 p0 = __ldg(&g_pair[i]);
        uint2 p1 = __ldg(&g_pair[i + 1]);
        float4 x0 = __ldg(x4 + (size_t)p0.x * 16 + q);
        float4 x1 = __ldg(x4 + (size_t)p1.x * 16 + q);
        float c0 = __uint_as_float(p0.y);
        float c1 = __uint_as_float(p1.y);
        acc.x += c0 * x0.x; acc.y += c0 * x0.y;
        acc.z += c0 * x0.z; acc.w += c0 * x0.w;
        acc.x += c1 * x1.x; acc.y += c1 * x1.y;
        acc.z += c1 * x1.z; acc.w += c1 * x1.w;
    }
    if (i < end) {
        uint2 p0 = __ldg(&g_pair[i]);
        float4 x0 = __ldg(x4 + (size_t)p0.x * 16 + q);
        float c0 = __uint_as_float(p0.y);
        acc.x += c0 * x0.x; acc.y += c0 * x0.y;
        acc.z += c0 * x0.z; acc.w += c0 * x0.w;
    }

    out4[(size_t)node * 16 + q] = acc;
}

// ---------------------------------------------------------------------------
// Launch.
// Inputs: x[N*64] f32, w_src[64] f32, w_dst[64] f32, ew[E] f32,
//         src_idx[E] i32, dst_idx[E] i32.  Output: h[N*64] f32.
// ---------------------------------------------------------------------------
extern "C" void kernel_launch(void* const* d_in, const int* in_sizes, int n_in,
                              void* d_out, int out_size) {
    const float* x     = (const float*)d_in[0];
    const float* w_src = (const float*)d_in[1];
    const float* w_dst = (const float*)d_in[2];
    const float* ew    = (const float*)d_in[3];
    const int*   s_idx = (const int*)d_in[4];
    const int*   d_idx = (const int*)d_in[5];
    float* out = (float*)d_out;

    int n_nodes = in_sizes[0] / 64;
    int n_edges = in_sizes[3];

    // Zero the dst histogram.
    void* cnt_ptr = nullptr;
    cudaGetSymbolAddress(&cnt_ptr, g_cnt);
    cudaMemsetAsync(cnt_ptr, 0, sizeof(int) * (size_t)n_nodes);

    {   // fused scores + hist/rank: needs max(n_nodes*16, n_edges) threads
        long long total = (long long)n_nodes * 16;
        if ((long long)n_edges > total) total = n_edges;
        int blocks = (int)((total + 255) / 256);
        scores_hist_kernel<<<blocks, 256>>>((const float4*)x, (const float4*)w_src,
                                            (const float4*)w_dst, d_idx,
                                            n_nodes, n_edges);
    }
    {   // two-phase prefix scan
        int nb = (n_nodes + SCAN_BLK - 1) / SCAN_BLK;
        scanA_kernel<<<nb, SCAN_BLK>>>(n_nodes);
        scanB_kernel<<<1, 512>>>(nb);
    }
    {   // permute with fused coefficient computation (atomic-free)
        int blocks = (n_edges + 255) / 256;
        permute_kernel<<<blocks, 256>>>(s_idx, d_idx, ew, n_edges);
    }
    {   // aggregate: 16 threads/node
        long long total = (long long)n_nodes * 16;
        int blocks = (int)((total + 255) / 256);
        aggregate_kernel<<<blocks, 256>>>((const float4*)x, (float4*)out,
                                          n_nodes, n_edges);
    }
}